// round 3
// baseline (speedup 1.0000x reference)
#include <cuda_runtime.h>
#include <cstdint>

#define N_NODES 2048
#define F_FEAT  64
#define H_HID   64
#define C_OUT   8

// ---------------- device scratch (no allocations allowed) ----------------
__device__ float g_bp[128];             // sorted breakpoints (64 real + 64 x +inf pad)
__device__ float g_A[65];               // per-segment slope
__device__ float g_B[65];               // per-segment intercept
__device__ float g_bias[C_OUT];         // sum_f b2[f,c]
__device__ float g_gT[C_OUT * N_NODES]; // g transposed: [c][j], bias included

// ---------------------------------------------------------------------------
// Setup: build the piecewise-linear representation of
//   m(d) = sum_h Wm2[h]*relu(Wm1[h]*d + bm1[h]) + bm2
// m is PWL in d with breakpoints t_h = -bm1[h]/Wm1[h].
// Segment k = #(sorted_bp < d) in [0,64]:  m = A[k]*d + B[k].
// Also compute bias[c] = sum_f b2[f,c].
// ---------------------------------------------------------------------------
__global__ void setup_kernel(const float* __restrict__ Wm1,
                             const float* __restrict__ bm1,
                             const float* __restrict__ Wm2,
                             const float* __restrict__ bm2,
                             const float* __restrict__ b2) {
    __shared__ float bp[64], dA[64], dB[64];
    __shared__ float sbp[64], sdA[64], sdB[64];
    __shared__ float bAv[64], bBv[64];

    int h = threadIdx.x;  // blockDim.x == 64
    float a = Wm1[h], b = bm1[h], c = Wm2[h];

    float t, da = 0.f, db = 0.f, bA = 0.f, bB = 0.f;
    if (a != 0.f) {
        t = -b / a;
        float pa = a * c, pb = b * c;
        if (a > 0.f) {           // becomes active when d crosses t upward
            da = pa; db = pb;
        } else {                 // active below t; deactivates crossing up
            da = -pa; db = -pb;
            bA = pa;  bB = pb;   // contributes in base (d = -inf) state
        }
    } else {
        t = __int_as_float(0x7f800000);  // +inf: never crossed
        if (b > 0.f) bB = b * c;         // constant active term
    }
    bp[h] = t; dA[h] = da; dB[h] = db; bAv[h] = bA; bBv[h] = bB;
    __syncthreads();

    // rank sort (ties broken by index)
    int rank = 0;
    for (int h2 = 0; h2 < 64; h2++) {
        float o = bp[h2];
        rank += (o < t) || (o == t && h2 < h);
    }
    sbp[rank] = t; sdA[rank] = da; sdB[rank] = db;
    __syncthreads();

    if (h == 0) {
        float A = 0.f, B = bm2[0];
        for (int i = 0; i < 64; i++) { A += bAv[i]; B += bBv[i]; }
        g_A[0] = A; g_B[0] = B;
        for (int k = 0; k < 64; k++) {
            A += sdA[k]; B += sdB[k];
            g_A[k + 1] = A; g_B[k + 1] = B;
            g_bp[k] = sbp[k];
        }
    }
    // pad upper half of breakpoint table with +inf (sentinel for 7-step search)
    g_bp[64 + h] = __int_as_float(0x7f800000);

    if (h < C_OUT) {
        float s = 0.f;
        for (int f = 0; f < F_FEAT; f++) s += b2[f * C_OUT + h];
        g_bias[h] = s;
    }
}

// ---------------------------------------------------------------------------
// g kernel: g[j,c] = sum_f sum_h relu(x[j,f]*W1[f,h]+b1[f,h]) * W2[f,h,c]
//                    + bias[c]
// One warp per row j; lane covers h = {lane, lane+32}; 8 fp32 accumulators;
// warp butterfly reduce; store transposed into g_gT[c][j].
// ---------------------------------------------------------------------------
__global__ void __launch_bounds__(256) g_kernel(const float* __restrict__ x,
                                                const float* __restrict__ W1,
                                                const float* __restrict__ b1,
                                                const float* __restrict__ W2) {
    int lane = threadIdx.x & 31;
    int n = blockIdx.x * 8 + (threadIdx.x >> 5);

    // preload this row of x; broadcast per-f via shfl
    float xr0 = x[n * F_FEAT + lane];
    float xr1 = x[n * F_FEAT + lane + 32];

    int h0 = lane, h1 = lane + 32;
    float acc[C_OUT];
#pragma unroll
    for (int c = 0; c < C_OUT; c++) acc[c] = 0.f;

#pragma unroll 2
    for (int f = 0; f < F_FEAT; f++) {
        float xsrc = (f < 32) ? xr0 : xr1;
        float xv = __shfl_sync(0xffffffffu, xsrc, f & 31);

        float ha = fmaxf(fmaf(xv, W1[f * 64 + h0], b1[f * 64 + h0]), 0.f);
        float hb = fmaxf(fmaf(xv, W1[f * 64 + h1], b1[f * 64 + h1]), 0.f);

        const float4* wa = (const float4*)(W2 + (size_t)(f * 64 + h0) * 8);
        const float4* wb = (const float4*)(W2 + (size_t)(f * 64 + h1) * 8);
        float4 a0 = wa[0], a1 = wa[1];
        float4 b0 = wb[0], b1v = wb[1];

        acc[0] = fmaf(ha, a0.x, fmaf(hb, b0.x,  acc[0]));
        acc[1] = fmaf(ha, a0.y, fmaf(hb, b0.y,  acc[1]));
        acc[2] = fmaf(ha, a0.z, fmaf(hb, b0.z,  acc[2]));
        acc[3] = fmaf(ha, a0.w, fmaf(hb, b0.w,  acc[3]));
        acc[4] = fmaf(ha, a1.x, fmaf(hb, b1v.x, acc[4]));
        acc[5] = fmaf(ha, a1.y, fmaf(hb, b1v.y, acc[5]));
        acc[6] = fmaf(ha, a1.z, fmaf(hb, b1v.z, acc[6]));
        acc[7] = fmaf(ha, a1.w, fmaf(hb, b1v.w, acc[7]));
    }

#pragma unroll
    for (int c = 0; c < C_OUT; c++)
#pragma unroll
        for (int o = 16; o; o >>= 1)
            acc[c] += __shfl_xor_sync(0xffffffffu, acc[c], o);

    if (lane == 0) {
#pragma unroll
        for (int c = 0; c < C_OUT; c++)
            g_gT[c * N_NODES + n] = acc[c] + g_bias[c];
    }
}

// ---------------------------------------------------------------------------
// Main kernel: out[i,c] = sum_j m(nd[i,j]/nm[i,j]) * g[j,c]
// m evaluated via PWL table: 7-step binary search over 128-entry padded
// breakpoint table (k = exact count of bp < d, in [0,64]) + 1 FMA.
// 256 blocks x 8 warps; warp-per-row; gT staged in shared (64KB, float4
// conflict-free); float4 streaming loads of nd/nm; warp butterfly reduce.
// ---------------------------------------------------------------------------
__global__ void __launch_bounds__(256) main_kernel(const float* __restrict__ nd,
                                                   const float* __restrict__ nm,
                                                   float* __restrict__ out) {
    extern __shared__ float sh[];
    float* gTs = sh;                       // [8][2048]
    float* bps = sh + C_OUT * N_NODES;     // [128] (padded)
    float* As  = bps + 128;                // [65]
    float* Bs  = As + 65;                  // [65]

    int tid = threadIdx.x;
    for (int i = tid; i < C_OUT * N_NODES; i += 256) gTs[i] = g_gT[i];
    if (tid < 128) bps[tid] = g_bp[tid];
    if (tid < 65) { As[tid] = g_A[tid]; Bs[tid] = g_B[tid]; }
    __syncthreads();

    int warp = tid >> 5, lane = tid & 31;
    int row = blockIdx.x * 8 + warp;

    const float* drow = nd + (size_t)row * N_NODES;
    const float* nrow = nm + (size_t)row * N_NODES;

    float acc[C_OUT];
#pragma unroll
    for (int c = 0; c < C_OUT; c++) acc[c] = 0.f;

#pragma unroll 2
    for (int jb = lane * 4; jb < N_NODES; jb += 128) {
        float4 dq = *(const float4*)(drow + jb);
        float4 nq = *(const float4*)(nrow + jb);
        float dv[4] = {dq.x, dq.y, dq.z, dq.w};
        float nv[4] = {nq.x, nq.y, nq.z, nq.w};

        float m[4];
#pragma unroll
        for (int t = 0; t < 4; t++) {
            float d = __fdividef(dv[t], nv[t]);
            // 7-step lower-bound over 128 padded entries -> k in [0,64]
            int k = 0;
#pragma unroll
            for (int s = 64; s >= 1; s >>= 1)
                if (bps[k + s - 1] < d) k += s;
            m[t] = fmaf(As[k], d, Bs[k]);
        }

#pragma unroll
        for (int c = 0; c < C_OUT; c++) {
            float4 gv = *(const float4*)(gTs + c * N_NODES + jb);
            acc[c] = fmaf(m[0], gv.x, acc[c]);
            acc[c] = fmaf(m[1], gv.y, acc[c]);
            acc[c] = fmaf(m[2], gv.z, acc[c]);
            acc[c] = fmaf(m[3], gv.w, acc[c]);
        }
    }

#pragma unroll
    for (int c = 0; c < C_OUT; c++)
#pragma unroll
        for (int o = 16; o; o >>= 1)
            acc[c] += __shfl_xor_sync(0xffffffffu, acc[c], o);

    if (lane == 0) {
#pragma unroll
        for (int c = 0; c < C_OUT; c++)
            out[row * C_OUT + c] = acc[c];
    }
}

// ---------------------------------------------------------------------------
extern "C" void kernel_launch(void* const* d_in, const int* in_sizes, int n_in,
                              void* d_out, int out_size) {
    const float* x   = (const float*)d_in[0];
    const float* nd  = (const float*)d_in[1];
    const float* nm  = (const float*)d_in[2];
    const float* W1  = (const float*)d_in[3];
    const float* b1  = (const float*)d_in[4];
    const float* W2  = (const float*)d_in[5];
    const float* b2  = (const float*)d_in[6];
    const float* Wm1 = (const float*)d_in[7];
    const float* bm1 = (const float*)d_in[8];
    const float* Wm2 = (const float*)d_in[9];
    const float* bm2 = (const float*)d_in[10];
    float* out = (float*)d_out;

    size_t shmem = (size_t)(C_OUT * N_NODES + 128 + 65 + 65) * sizeof(float);
    cudaFuncSetAttribute(main_kernel, cudaFuncAttributeMaxDynamicSharedMemorySize,
                         (int)shmem);

    setup_kernel<<<1, 64>>>(Wm1, bm1, Wm2, bm2, b2);
    g_kernel<<<N_NODES / 8, 256>>>(x, W1, b1, W2);
    main_kernel<<<N_NODES / 8, 256, shmem>>>(nd, nm, out);
}